// round 1
// baseline (speedup 1.0000x reference)
#include <cuda_runtime.h>
#include <math.h>
#include <stdint.h>

#define BB 2
#define TT 1024
#define CC 1024
#define HH 8
#define HD 128
#define LL 4
#define FFD 100
#define VV 32000
#define NTOK (BB*TT)
#define SCALE 0.08838834764831845f  /* 1/sqrt(128) */
#define LN_EPS 1e-5f

#define BM 64
#define BN 64
#define BK 16

// ---------------- scratch (static device arrays; no allocation) ----------------
__device__ float g_h [NTOK*CC];
__device__ float g_hn[NTOK*CC];
__device__ float g_q [NTOK*CC];
__device__ float g_k [NTOK*CC];
__device__ float g_v [NTOK*CC];
__device__ float g_o [NTOK*CC];
__device__ float g_ff[NTOK*FFD];

// ---------------- embedding ----------------
__global__ void embed_kernel(const int* __restrict__ x, const float* __restrict__ emb,
                             float* __restrict__ h)
{
    int idx = blockIdx.x * blockDim.x + threadIdx.x;
    if (idx < NTOK*CC) {
        int n = idx / CC, c = idx % CC;
        h[idx] = emb[(size_t)x[n]*CC + c];
    }
}

// ---------------- layernorm (block per row) ----------------
__global__ void ln_kernel(const float* __restrict__ in, const float* __restrict__ g,
                          const float* __restrict__ b, float* __restrict__ out)
{
    int row = blockIdx.x;
    const float* xr = in + (size_t)row*CC;
    __shared__ float red[256];
    int tid = threadIdx.x;

    float s = 0.f;
    for (int c = tid; c < CC; c += 256) s += xr[c];
    red[tid] = s; __syncthreads();
    for (int q = 128; q > 0; q >>= 1) { if (tid < q) red[tid] += red[tid+q]; __syncthreads(); }
    float mu = red[0] * (1.f/CC);
    __syncthreads();

    float v = 0.f;
    for (int c = tid; c < CC; c += 256) { float d = xr[c]-mu; v += d*d; }
    red[tid] = v; __syncthreads();
    for (int q = 128; q > 0; q >>= 1) { if (tid < q) red[tid] += red[tid+q]; __syncthreads(); }
    float rstd = rsqrtf(red[0] * (1.f/CC) + LN_EPS);

    for (int c = tid; c < CC; c += 256)
        out[(size_t)row*CC + c] = (xr[c]-mu)*rstd*g[c] + b[c];
}

// ---------------- generic NN GEMM: C = A[MxK] * B[KxN] (+bias) (+add) (relu?) ----------------
template<bool RELU, bool ADD>
__global__ void gemm_nn_kernel(const float* __restrict__ A, int lda,
                               const float* __restrict__ Bm, int ldb,
                               const float* __restrict__ bias,
                               const float* __restrict__ addp, int ldadd,
                               float* __restrict__ Cm, int ldc,
                               int M, int N, int K)
{
    __shared__ float As[BK][BM];
    __shared__ float Bs[BK][BN];
    int tid = threadIdx.x;
    int tx = tid & 15, ty = tid >> 4;
    int m0 = blockIdx.y * BM;
    int n0 = blockIdx.x * BN;
    float acc[4][4] = {};

    for (int k0 = 0; k0 < K; k0 += BK) {
        #pragma unroll
        for (int i = 0; i < 4; i++) {
            int e = tid + 256*i;
            int r = e >> 4, c = e & 15;
            int gm = m0 + r, gk = k0 + c;
            As[c][r] = (gm < M && gk < K) ? A[(size_t)gm*lda + gk] : 0.f;
        }
        #pragma unroll
        for (int i = 0; i < 4; i++) {
            int e = tid + 256*i;
            int r = e >> 6, c = e & 63;
            int gk = k0 + r, gn = n0 + c;
            Bs[r][c] = (gk < K && gn < N) ? Bm[(size_t)gk*ldb + gn] : 0.f;
        }
        __syncthreads();
        #pragma unroll
        for (int k = 0; k < BK; k++) {
            float a[4], bq[4];
            #pragma unroll
            for (int i = 0; i < 4; i++) a[i]  = As[k][ty*4+i];
            #pragma unroll
            for (int j = 0; j < 4; j++) bq[j] = Bs[k][tx*4+j];
            #pragma unroll
            for (int i = 0; i < 4; i++)
                #pragma unroll
                for (int j = 0; j < 4; j++)
                    acc[i][j] += a[i]*bq[j];
        }
        __syncthreads();
    }

    #pragma unroll
    for (int i = 0; i < 4; i++) {
        int gm = m0 + ty*4 + i;
        if (gm >= M) continue;
        #pragma unroll
        for (int j = 0; j < 4; j++) {
            int gn = n0 + tx*4 + j;
            if (gn >= N) continue;
            float vv = acc[i][j];
            if (bias) vv += bias[gn];
            if (ADD)  vv += addp[(size_t)gm*ldadd + gn];
            if (RELU) vv = fmaxf(vv, 0.f);
            Cm[(size_t)gm*ldc + gn] = vv;
        }
    }
}

// ---------------- scores: S = Q Kᵀ * scale + alibi, causal mask; batched over b,h ----------------
__global__ void scores_kernel(const float* __restrict__ Qm, const float* __restrict__ Km,
                              float* __restrict__ attnL)
{
    int z = blockIdx.z;
    int b = z / HH, h = z % HH;
    const float* Aq = Qm + (size_t)b*TT*CC + h*HD;
    const float* Ak = Km + (size_t)b*TT*CC + h*HD;
    float* S = attnL + (size_t)z*TT*TT;
    float slope = exp2f(-(float)(h+1));
    int m0 = blockIdx.y * BM;
    int n0 = blockIdx.x * BN;
    int tid = threadIdx.x;
    int tx = tid & 15, ty = tid >> 4;

    if (n0 > m0 + (BM-1)) {      // fully masked tile
        #pragma unroll
        for (int i = 0; i < 4; i++) {
            int ig = m0 + ty*4 + i;
            #pragma unroll
            for (int j = 0; j < 4; j++)
                S[(size_t)ig*TT + n0 + tx*4 + j] = -INFINITY;
        }
        return;
    }

    __shared__ float As[BK][BM];
    __shared__ float Bs[BK][BN];
    float acc[4][4] = {};

    for (int k0 = 0; k0 < HD; k0 += BK) {
        #pragma unroll
        for (int i = 0; i < 4; i++) {
            int e = tid + 256*i;
            int r = e >> 4, c = e & 15;
            As[c][r] = Aq[(size_t)(m0+r)*CC + k0 + c];
        }
        #pragma unroll
        for (int i = 0; i < 4; i++) {
            int e = tid + 256*i;
            int nn = e >> 4, c = e & 15;
            Bs[c][nn] = Ak[(size_t)(n0+nn)*CC + k0 + c];
        }
        __syncthreads();
        #pragma unroll
        for (int k = 0; k < BK; k++) {
            float a[4], bq[4];
            #pragma unroll
            for (int i = 0; i < 4; i++) a[i]  = As[k][ty*4+i];
            #pragma unroll
            for (int j = 0; j < 4; j++) bq[j] = Bs[k][tx*4+j];
            #pragma unroll
            for (int i = 0; i < 4; i++)
                #pragma unroll
                for (int j = 0; j < 4; j++)
                    acc[i][j] += a[i]*bq[j];
        }
        __syncthreads();
    }

    #pragma unroll
    for (int i = 0; i < 4; i++) {
        int ig = m0 + ty*4 + i;
        #pragma unroll
        for (int j = 0; j < 4; j++) {
            int jg = n0 + tx*4 + j;
            float vv = (jg <= ig) ? (acc[i][j]*SCALE + slope*(float)(jg-ig)) : -INFINITY;
            S[(size_t)ig*TT + jg] = vv;
        }
    }
}

// ---------------- softmax in-place (block per row of T) ----------------
__global__ void softmax_kernel(float* __restrict__ attnL)
{
    size_t row = blockIdx.x;
    float* r = attnL + row * TT;
    __shared__ float red[256];
    int tid = threadIdx.x;

    float m = -INFINITY;
    for (int c = tid; c < TT; c += 256) m = fmaxf(m, r[c]);
    red[tid] = m; __syncthreads();
    for (int q = 128; q > 0; q >>= 1) { if (tid < q) red[tid] = fmaxf(red[tid], red[tid+q]); __syncthreads(); }
    m = red[0]; __syncthreads();

    float s = 0.f;
    for (int c = tid; c < TT; c += 256) { float e = expf(r[c]-m); r[c] = e; s += e; }
    red[tid] = s; __syncthreads();
    for (int q = 128; q > 0; q >>= 1) { if (tid < q) red[tid] += red[tid+q]; __syncthreads(); }
    float inv = 1.f / red[0];

    for (int c = tid; c < TT; c += 256) r[c] *= inv;
}

// ---------------- O = attn @ V, batched over b,h, causal k-bound ----------------
__global__ void av_kernel(const float* __restrict__ attnL, const float* __restrict__ Vm,
                          float* __restrict__ Om)
{
    int z = blockIdx.z;
    int b = z / HH, h = z % HH;
    const float* A  = attnL + (size_t)z*TT*TT;
    const float* Bm = Vm + (size_t)b*TT*CC + h*HD;
    float*       Cm = Om + (size_t)b*TT*CC + h*HD;
    int m0 = blockIdx.y * BM;
    int n0 = blockIdx.x * BN;
    int tid = threadIdx.x;
    int tx = tid & 15, ty = tid >> 4;
    int kmax = m0 + BM;   // attn[i][j]==0 for j>i

    __shared__ float As[BK][BM];
    __shared__ float Bs[BK][BN];
    float acc[4][4] = {};

    for (int k0 = 0; k0 < kmax; k0 += BK) {
        #pragma unroll
        for (int i = 0; i < 4; i++) {
            int e = tid + 256*i;
            int r = e >> 4, c = e & 15;
            As[c][r] = A[(size_t)(m0+r)*TT + k0 + c];
        }
        #pragma unroll
        for (int i = 0; i < 4; i++) {
            int e = tid + 256*i;
            int r = e >> 6, c = e & 63;
            Bs[r][c] = Bm[(size_t)(k0+r)*CC + n0 + c];
        }
        __syncthreads();
        #pragma unroll
        for (int k = 0; k < BK; k++) {
            float a[4], bq[4];
            #pragma unroll
            for (int i = 0; i < 4; i++) a[i]  = As[k][ty*4+i];
            #pragma unroll
            for (int j = 0; j < 4; j++) bq[j] = Bs[k][tx*4+j];
            #pragma unroll
            for (int i = 0; i < 4; i++)
                #pragma unroll
                for (int j = 0; j < 4; j++)
                    acc[i][j] += a[i]*bq[j];
        }
        __syncthreads();
    }

    #pragma unroll
    for (int i = 0; i < 4; i++) {
        int gm = m0 + ty*4 + i;
        #pragma unroll
        for (int j = 0; j < 4; j++)
            Cm[(size_t)gm*CC + n0 + tx*4 + j] = acc[i][j];
    }
}

// ---------------- host ----------------
extern "C" void kernel_launch(void* const* d_in, const int* in_sizes, int n_in,
                              void* d_out, int out_size)
{
    const int*   x    = (const int*)  d_in[0];
    const float* emb  = (const float*)d_in[1];
    const float* Wq   = (const float*)d_in[2];
    const float* bq   = (const float*)d_in[3];
    const float* Wk   = (const float*)d_in[4];
    const float* bk   = (const float*)d_in[5];
    const float* Wv   = (const float*)d_in[6];
    const float* bv   = (const float*)d_in[7];
    const float* Wo   = (const float*)d_in[8];
    const float* bo   = (const float*)d_in[9];
    const float* W1   = (const float*)d_in[10];
    const float* b1   = (const float*)d_in[11];
    const float* W2   = (const float*)d_in[12];
    const float* b2   = (const float*)d_in[13];
    const float* ln1g = (const float*)d_in[14];
    const float* ln1b = (const float*)d_in[15];
    const float* ln3g = (const float*)d_in[16];
    const float* ln3b = (const float*)d_in[17];
    const float* lnfg = (const float*)d_in[18];
    const float* lnfb = (const float*)d_in[19];
    const float* Wout = (const float*)d_in[20];
    const float* bout = (const float*)d_in[21];

    float* out_logits = (float*)d_out;                               // [B,T,V]
    float* out_attn   = out_logits + (size_t)BB*TT*VV;               // [L,B,H,T,T]

    float *h, *hn, *q, *k, *v, *o, *ff;
    cudaGetSymbolAddress((void**)&h,  g_h);
    cudaGetSymbolAddress((void**)&hn, g_hn);
    cudaGetSymbolAddress((void**)&q,  g_q);
    cudaGetSymbolAddress((void**)&k,  g_k);
    cudaGetSymbolAddress((void**)&v,  g_v);
    cudaGetSymbolAddress((void**)&o,  g_o);
    cudaGetSymbolAddress((void**)&ff, g_ff);

    // embedding
    embed_kernel<<<(NTOK*CC + 255)/256, 256>>>(x, emb, h);

    dim3 thr(256);
    dim3 gC(CC/BN, NTOK/BM);          // 16 x 32 : [2048 x 1024] dense outputs
    dim3 gS(TT/BN, TT/BM, BB*HH);     // scores
    dim3 gAV(HD/BN, TT/BM, BB*HH);    // attn @ V

    for (int l = 0; l < LL; l++) {
        float* attnL = out_attn + (size_t)l*BB*HH*TT*TT;

        ln_kernel<<<NTOK, 256>>>(h, ln1g + l*CC, ln1b + l*CC, hn);

        gemm_nn_kernel<false,false><<<gC, thr>>>(hn, CC, Wq + (size_t)l*CC*CC, CC,
                                                 bq + l*CC, nullptr, 0, q, CC, NTOK, CC, CC);
        gemm_nn_kernel<false,false><<<gC, thr>>>(hn, CC, Wk + (size_t)l*CC*CC, CC,
                                                 bk + l*CC, nullptr, 0, k, CC, NTOK, CC, CC);
        gemm_nn_kernel<false,false><<<gC, thr>>>(hn, CC, Wv + (size_t)l*CC*CC, CC,
                                                 bv + l*CC, nullptr, 0, v, CC, NTOK, CC, CC);

        scores_kernel<<<gS, thr>>>(q, k, attnL);
        softmax_kernel<<<BB*HH*TT, 256>>>(attnL);
        av_kernel<<<gAV, thr>>>(attnL, v, o);

        // h = h + o @ Wo + bo
        gemm_nn_kernel<false,true><<<gC, thr>>>(o, CC, Wo + (size_t)l*CC*CC, CC,
                                                bo + l*CC, h, CC, h, CC, NTOK, CC, CC);

        ln_kernel<<<NTOK, 256>>>(h, ln3g + l*CC, ln3b + l*CC, hn);

        // ff = relu(hn @ W1 + b1)
        dim3 gF1((FFD + BN - 1)/BN, NTOK/BM);
        gemm_nn_kernel<true,false><<<gF1, thr>>>(hn, CC, W1 + (size_t)l*CC*FFD, FFD,
                                                 b1 + l*FFD, nullptr, 0, ff, FFD, NTOK, FFD, CC);
        // h = h + ff @ W2 + b2
        gemm_nn_kernel<false,true><<<gC, thr>>>(ff, FFD, W2 + (size_t)l*FFD*CC, CC,
                                                b2 + l*CC, h, CC, h, CC, NTOK, CC, FFD);
    }

    // final LN + logits
    ln_kernel<<<NTOK, 256>>>(h, lnfg, lnfb, hn);
    dim3 gL(VV/BN, NTOK/BM);
    gemm_nn_kernel<false,false><<<gL, thr>>>(hn, CC, Wout, VV,
                                             bout, nullptr, 0, out_logits, VV, NTOK, VV, CC);
}

// round 3
// speedup vs baseline: 2.4817x; 2.4817x over previous
#include <cuda_runtime.h>
#include <math.h>
#include <stdint.h>

#define BB 2
#define TT 1024
#define CC 1024
#define HH 8
#define HD 128
#define LL 4
#define FFD 100
#define FFP 128          /* padded leading dim for ff scratch */
#define VV 32000
#define NTOK (BB*TT)
#define SCALE 0.08838834764831845f  /* 1/sqrt(128) */
#define LN_EPS 1e-5f

#define TM 128
#define TN 128
#define TK 8

typedef unsigned long long u64;

// ---------------- scratch ----------------
__device__ float g_h [NTOK*CC];
__device__ float g_hn[NTOK*CC];
__device__ float g_q [NTOK*CC];
__device__ float g_k [NTOK*CC];
__device__ float g_v [NTOK*CC];
__device__ float g_o [NTOK*CC];
__device__ float g_ff[NTOK*FFP];

// ---------------- f32x2 helpers ----------------
__device__ __forceinline__ u64 dup2(float a) {
    u64 r; asm("mov.b64 %0, {%1, %1};" : "=l"(r) : "f"(a)); return r;
}
__device__ __forceinline__ void fma2(u64& d, u64 a, u64 b) {
    asm("fma.rn.f32x2 %0, %1, %2, %0;" : "+l"(d) : "l"(a), "l"(b));
}
__device__ __forceinline__ float2 asf2(u64 v) {
    float2 p; asm("mov.b64 {%0, %1}, %2;" : "=f"(p.x), "=f"(p.y) : "l"(v)); return p;
}

// 8x8 per-thread tile MAC on packed pairs (cols packed in pairs)
__device__ __forceinline__ void mm_tile(const float (*As)[TM], const float (*Bs)[TN],
                                        u64 acc[8][4], int ty, int tx)
{
    #pragma unroll
    for (int k = 0; k < TK; k++) {
        float4 a0 = *(const float4*)&As[k][ty*8];
        float4 a1 = *(const float4*)&As[k][ty*8+4];
        u64 b0 = *(const u64*)&Bs[k][tx*4];
        u64 b1 = *(const u64*)&Bs[k][tx*4+2];
        u64 b2 = *(const u64*)&Bs[k][64+tx*4];
        u64 b3 = *(const u64*)&Bs[k][64+tx*4+2];
        float av[8] = {a0.x,a0.y,a0.z,a0.w,a1.x,a1.y,a1.z,a1.w};
        #pragma unroll
        for (int i = 0; i < 8; i++) {
            u64 ad = dup2(av[i]);
            fma2(acc[i][0], ad, b0);
            fma2(acc[i][1], ad, b1);
            fma2(acc[i][2], ad, b2);
            fma2(acc[i][3], ad, b3);
        }
    }
}

// ---------------- embedding (float4) ----------------
__global__ void embed_kernel(const int* __restrict__ x, const float* __restrict__ emb,
                             float* __restrict__ h)
{
    int idx = blockIdx.x * 256 + threadIdx.x;      // NTOK*256 float4s
    int n = idx >> 8, c = idx & 255;
    ((float4*)h)[idx] = ((const float4*)emb)[(size_t)x[n]*(CC/4) + c];
}

// ---------------- layernorm: 1 block per row, 256 thr x float4 ----------------
__global__ void ln_kernel(const float* __restrict__ in, const float* __restrict__ g,
                          const float* __restrict__ b, float* __restrict__ out)
{
    int row = blockIdx.x, tid = threadIdx.x;
    const float4* xr = (const float4*)(in + (size_t)row*CC);
    float4 x = xr[tid];
    __shared__ float red[32];

    float s = x.x + x.y + x.z + x.w;
    #pragma unroll
    for (int o = 16; o; o >>= 1) s += __shfl_xor_sync(0xffffffffu, s, o);
    if ((tid & 31) == 0) red[tid >> 5] = s;
    __syncthreads();
    if (tid == 0) {
        float t = 0.f;
        #pragma unroll
        for (int w = 0; w < 8; w++) t += red[w];
        red[0] = t;
    }
    __syncthreads();
    float mu = red[0] * (1.f/CC);
    __syncthreads();

    float4 d = make_float4(x.x-mu, x.y-mu, x.z-mu, x.w-mu);
    float v = d.x*d.x + d.y*d.y + d.z*d.z + d.w*d.w;
    #pragma unroll
    for (int o = 16; o; o >>= 1) v += __shfl_xor_sync(0xffffffffu, v, o);
    if ((tid & 31) == 0) red[tid >> 5] = v;
    __syncthreads();
    if (tid == 0) {
        float t = 0.f;
        #pragma unroll
        for (int w = 0; w < 8; w++) t += red[w];
        red[0] = t;
    }
    __syncthreads();
    float rstd = rsqrtf(red[0] * (1.f/CC) + LN_EPS);

    float4 gg = ((const float4*)g)[tid];
    float4 bb = ((const float4*)b)[tid];
    float4 o4;
    o4.x = d.x*rstd*gg.x + bb.x;
    o4.y = d.y*rstd*gg.y + bb.y;
    o4.z = d.z*rstd*gg.z + bb.z;
    o4.w = d.w*rstd*gg.w + bb.w;
    ((float4*)(out + (size_t)row*CC))[tid] = o4;
}

// ---------------- generic 128x128x8 GEMM: C = A[MxK]*B[KxN] (+bias)(+add)(relu) ----------------
// M must be a multiple of 128. K,N multiples of 4. NG => guard N (and scalar B loads).
template<bool RELU, bool ADD, bool NG>
__global__ __launch_bounds__(256, 2)
void sgemm_kernel(const float* __restrict__ A, int lda,
                  const float* __restrict__ B, int ldb,
                  const float* __restrict__ bias,
                  const float* __restrict__ addp, int ldadd,
                  float* __restrict__ C, int ldc,
                  int N, int K)
{
    __shared__ float As[TK][TM];
    __shared__ float Bs[TK][TN];
    int tid = threadIdx.x;
    int m0 = blockIdx.y * TM, n0 = blockIdx.x * TN;
    int arow = tid >> 1, acol = (tid & 1) * 4;
    int brow = tid >> 5, bcol = (tid & 31) * 4;
    int tx = tid & 15, ty = tid >> 4;

    u64 acc[8][4];
    #pragma unroll
    for (int i = 0; i < 8; i++)
        #pragma unroll
        for (int j = 0; j < 4; j++) acc[i][j] = 0ull;

    const float* Ap = A + (size_t)(m0 + arow) * lda;
    float4 aR, bR;
    const float4 z4 = make_float4(0.f,0.f,0.f,0.f);

    // prologue loads
    aR = (acol < K) ? *(const float4*)&Ap[acol] : z4;
    if (!NG) {
        bR = (brow < K) ? *(const float4*)&B[(size_t)brow*ldb + n0 + bcol] : z4;
    } else {
        bR = z4;
        if (brow < K) {
            const float* bp = B + (size_t)brow*ldb;
            int n = n0 + bcol;
            if (n+0 < N) bR.x = bp[n+0];
            if (n+1 < N) bR.y = bp[n+1];
            if (n+2 < N) bR.z = bp[n+2];
            if (n+3 < N) bR.w = bp[n+3];
        }
    }

    for (int k0 = 0; k0 < K; k0 += TK) {
        As[acol+0][arow] = aR.x; As[acol+1][arow] = aR.y;
        As[acol+2][arow] = aR.z; As[acol+3][arow] = aR.w;
        *(float4*)&Bs[brow][bcol] = bR;
        __syncthreads();

        int kn = k0 + TK;
        if (kn < K) {
            aR = (kn + acol < K) ? *(const float4*)&Ap[kn + acol] : z4;
            if (!NG) {
                bR = (kn + brow < K) ? *(const float4*)&B[(size_t)(kn+brow)*ldb + n0 + bcol] : z4;
            } else {
                bR = z4;
                if (kn + brow < K) {
                    const float* bp = B + (size_t)(kn+brow)*ldb;
                    int n = n0 + bcol;
                    if (n+0 < N) bR.x = bp[n+0];
                    if (n+1 < N) bR.y = bp[n+1];
                    if (n+2 < N) bR.z = bp[n+2];
                    if (n+3 < N) bR.w = bp[n+3];
                }
            }
        }
        mm_tile(As, Bs, acc, ty, tx);
        __syncthreads();
    }

    #pragma unroll
    for (int i = 0; i < 8; i++) {
        int gm = m0 + ty*8 + i;
        float v[8];
        #pragma unroll
        for (int jp = 0; jp < 4; jp++) {
            float2 p = asf2(acc[i][jp]);
            v[jp*2+0] = p.x; v[jp*2+1] = p.y;
        }
        if (!NG) {
            #pragma unroll
            for (int gq = 0; gq < 2; gq++) {
                int gn = n0 + gq*64 + tx*4;
                float4 bb = *(const float4*)&bias[gn];
                float4 o;
                o.x = v[gq*4+0] + bb.x; o.y = v[gq*4+1] + bb.y;
                o.z = v[gq*4+2] + bb.z; o.w = v[gq*4+3] + bb.w;
                if (ADD) {
                    float4 ap = *(const float4*)&addp[(size_t)gm*ldadd + gn];
                    o.x += ap.x; o.y += ap.y; o.z += ap.z; o.w += ap.w;
                }
                if (RELU) {
                    o.x = fmaxf(o.x, 0.f); o.y = fmaxf(o.y, 0.f);
                    o.z = fmaxf(o.z, 0.f); o.w = fmaxf(o.w, 0.f);
                }
                *(float4*)&C[(size_t)gm*ldc + gn] = o;
            }
        } else {
            #pragma unroll
            for (int j = 0; j < 8; j++) {
                int gn = n0 + (j < 4 ? 0 : 64) + tx*4 + (j & 3);
                if (gn < N) {
                    float vv = v[j] + bias[gn];
                    if (ADD) vv += addp[(size_t)gm*ldadd + gn];
                    if (RELU) vv = fmaxf(vv, 0.f);
                    C[(size_t)gm*ldc + gn] = vv;
                }
            }
        }
    }
}

// ---------------- scores: S = Q K^T * scale + alibi, causal -> 0 above diag ----------------
__global__ __launch_bounds__(256, 2)
void scores_kernel(const float* __restrict__ Q, const float* __restrict__ Kc,
                   float* __restrict__ attn)
{
    int zb = blockIdx.z, b = zb >> 3, h = zb & 7;
    int m0 = blockIdx.y * TM, n0 = blockIdx.x * TN;
    int tid = threadIdx.x, tx = tid & 15, ty = tid >> 4;
    float* S = attn + (size_t)zb * TT * TT;
    const float4 z4 = make_float4(0.f,0.f,0.f,0.f);

    if (n0 > m0) {   // fully above diagonal -> zeros
        #pragma unroll
        for (int i = 0; i < 8; i++) {
            int ig = m0 + ty*8 + i;
            *(float4*)&S[(size_t)ig*TT + n0 + tx*4] = z4;
            *(float4*)&S[(size_t)ig*TT + n0 + 64 + tx*4] = z4;
        }
        return;
    }

    const float* Aq = Q  + (size_t)b*TT*CC + h*HD;
    const float* Ak = Kc + (size_t)b*TT*CC + h*HD;
    __shared__ float As[TK][TM];
    __shared__ float Bs[TK][TN];
    int arow = tid >> 1, acol = (tid & 1) * 4;

    u64 acc[8][4];
    #pragma unroll
    for (int i = 0; i < 8; i++)
        #pragma unroll
        for (int j = 0; j < 4; j++) acc[i][j] = 0ull;

    float4 aR = *(const float4*)&Aq[(size_t)(m0+arow)*CC + acol];
    float4 bR = *(const float4*)&Ak[(size_t)(n0+arow)*CC + acol];

    for (int k0 = 0; k0 < HD; k0 += TK) {
        As[acol+0][arow] = aR.x; As[acol+1][arow] = aR.y;
        As[acol+2][arow] = aR.z; As[acol+3][arow] = aR.w;
        Bs[acol+0][arow] = bR.x; Bs[acol+1][arow] = bR.y;
        Bs[acol+2][arow] = bR.z; Bs[acol+3][arow] = bR.w;
        __syncthreads();
        int kn = k0 + TK;
        if (kn < HD) {
            aR = *(const float4*)&Aq[(size_t)(m0+arow)*CC + kn + acol];
            bR = *(const float4*)&Ak[(size_t)(n0+arow)*CC + kn + acol];
        }
        mm_tile(As, Bs, acc, ty, tx);
        __syncthreads();
    }

    float slope = exp2f(-(float)(h+1));
    #pragma unroll
    for (int i = 0; i < 8; i++) {
        int ig = m0 + ty*8 + i;
        float v[8];
        #pragma unroll
        for (int jp = 0; jp < 4; jp++) {
            float2 p = asf2(acc[i][jp]);
            v[jp*2+0] = p.x; v[jp*2+1] = p.y;
        }
        #pragma unroll
        for (int gq = 0; gq < 2; gq++) {
            int gn = n0 + gq*64 + tx*4;
            float4 o;
            float* ov = (float*)&o;
            #pragma unroll
            for (int j = 0; j < 4; j++) {
                int jg = gn + j;
                ov[j] = (jg <= ig) ? (v[gq*4+j]*SCALE + slope*(float)(jg-ig)) : 0.f;
            }
            *(float4*)&S[(size_t)ig*TT + gn] = o;
        }
    }
}

// ---------------- softmax over causal prefix (rest already 0) ----------------
__global__ void softmax_kernel(float* __restrict__ attnL)
{
    int rowid = blockIdx.x;
    int i = rowid & (TT-1);
    int L = i + 1;
    float* r = attnL + (size_t)rowid * TT;
    __shared__ float red[256];
    int tid = threadIdx.x;

    float m = -INFINITY;
    for (int c = tid; c < L; c += 256) m = fmaxf(m, r[c]);
    red[tid] = m; __syncthreads();
    for (int q = 128; q > 0; q >>= 1) { if (tid < q) red[tid] = fmaxf(red[tid], red[tid+q]); __syncthreads(); }
    m = red[0]; __syncthreads();

    float s = 0.f;
    for (int c = tid; c < L; c += 256) { float e = __expf(r[c]-m); r[c] = e; s += e; }
    red[tid] = s; __syncthreads();
    for (int q = 128; q > 0; q >>= 1) { if (tid < q) red[tid] += red[tid+q]; __syncthreads(); }
    float inv = 1.f / red[0];

    for (int c = tid; c < L; c += 256) r[c] *= inv;
}

// ---------------- O = attn @ V with causal k-bound ----------------
__global__ __launch_bounds__(256, 2)
void av_kernel(const float* __restrict__ attn, const float* __restrict__ V,
               float* __restrict__ O)
{
    int zb = blockIdx.z, b = zb >> 3, h = zb & 7;
    int m0 = blockIdx.y * TM;
    int tid = threadIdx.x, tx = tid & 15, ty = tid >> 4;
    const float* A  = attn + (size_t)zb * TT * TT;
    const float* Bv = V + (size_t)b*TT*CC + h*HD;
    float*       Co = O + (size_t)b*TT*CC + h*HD;
    int kEnd = m0 + TM;

    __shared__ float As[TK][TM];
    __shared__ float Bs[TK][TN];
    int arow = tid >> 1, acol = (tid & 1) * 4;
    int brow = tid >> 5, bcol = (tid & 31) * 4;

    u64 acc[8][4];
    #pragma unroll
    for (int i = 0; i < 8; i++)
        #pragma unroll
        for (int j = 0; j < 4; j++) acc[i][j] = 0ull;

    float4 aR = *(const float4*)&A[(size_t)(m0+arow)*TT + acol];
    float4 bR = *(const float4*)&Bv[(size_t)brow*CC + bcol];

    for (int k0 = 0; k0 < kEnd; k0 += TK) {
        As[acol+0][arow] = aR.x; As[acol+1][arow] = aR.y;
        As[acol+2][arow] = aR.z; As[acol+3][arow] = aR.w;
        *(float4*)&Bs[brow][bcol] = bR;
        __syncthreads();
        int kn = k0 + TK;
        if (kn < kEnd) {
            aR = *(const float4*)&A[(size_t)(m0+arow)*TT + kn + acol];
            bR = *(const float4*)&Bv[(size_t)(kn+brow)*CC + bcol];
        }
        mm_tile(As, Bs, acc, ty, tx);
        __syncthreads();
    }

    #pragma unroll
    for (int i = 0; i < 8; i++) {
        int gm = m0 + ty*8 + i;
        #pragma unroll
        for (int jp = 0; jp < 4; jp++) {
            float2 p = asf2(acc[i][jp]);
            int gn = (jp < 2) ? (tx*4 + jp*2) : (64 + tx*4 + (jp-2)*2);
            Co[(size_t)gm*CC + gn + 0] = p.x;
            Co[(size_t)gm*CC + gn + 1] = p.y;
        }
    }
}

// ---------------- host ----------------
extern "C" void kernel_launch(void* const* d_in, const int* in_sizes, int n_in,
                              void* d_out, int out_size)
{
    const int*   x    = (const int*)  d_in[0];
    const float* emb  = (const float*)d_in[1];
    const float* Wq   = (const float*)d_in[2];
    const float* bq   = (const float*)d_in[3];
    const float* Wk   = (const float*)d_in[4];
    const float* bk   = (const float*)d_in[5];
    const float* Wv   = (const float*)d_in[6];
    const float* bv   = (const float*)d_in[7];
    const float* Wo   = (const float*)d_in[8];
    const float* bo   = (const float*)d_in[9];
    const float* W1   = (const float*)d_in[10];
    const float* b1   = (const float*)d_in[11];
    const float* W2   = (const float*)d_in[12];
    const float* b2   = (const float*)d_in[13];
    const float* ln1g = (const float*)d_in[14];
    const float* ln1b = (const float*)d_in[15];
    const float* ln3g = (const float*)d_in[16];
    const float* ln3b = (const float*)d_in[17];
    const float* lnfg = (const float*)d_in[18];
    const float* lnfb = (const float*)d_in[19];
    const float* Wout = (const float*)d_in[20];
    const float* bout = (const float*)d_in[21];

    float* out_logits = (float*)d_out;                   // [B,T,V]
    float* out_attn   = out_logits + (size_t)BB*TT*VV;   // [L,B,H,T,T]

    float *h, *hn, *q, *k, *v, *o, *ff;
    cudaGetSymbolAddress((void**)&h,  g_h);
    cudaGetSymbolAddress((void**)&hn, g_hn);
    cudaGetSymbolAddress((void**)&q,  g_q);
    cudaGetSymbolAddress((void**)&k,  g_k);
    cudaGetSymbolAddress((void**)&v,  g_v);
    cudaGetSymbolAddress((void**)&o,  g_o);
    cudaGetSymbolAddress((void**)&ff, g_ff);

    embed_kernel<<<NTOK, 256>>>(x, emb, h);

    dim3 thr(256);
    dim3 gC(CC/TN, NTOK/TM);           // 8 x 16
    dim3 gS(TT/TN, TT/TM, BB*HH);      // 8 x 8 x 16
    dim3 gAV(1, TT/TM, BB*HH);         // 1 x 8 x 16
    dim3 gF1(1, NTOK/TM);
    dim3 gL(VV/TN, NTOK/TM);           // 250 x 16

    for (int l = 0; l < LL; l++) {
        float* attnL = out_attn + (size_t)l*BB*HH*TT*TT;

        ln_kernel<<<NTOK, 256>>>(h, ln1g + l*CC, ln1b + l*CC, hn);

        sgemm_kernel<false,false,false><<<gC, thr>>>(hn, CC, Wq + (size_t)l*CC*CC, CC,
                                                     bq + l*CC, nullptr, 0, q, CC, CC, CC);
        sgemm_kernel<false,false,false><<<gC, thr>>>(hn, CC, Wk + (size_t)l*CC*CC, CC,
                                                     bk + l*CC, nullptr, 0, k, CC, CC, CC);
        sgemm_kernel<false,false,false><<<gC, thr>>>(hn, CC, Wv + (size_t)l*CC*CC, CC,
                                                     bv + l*CC, nullptr, 0, v, CC, CC, CC);

        scores_kernel<<<gS, thr>>>(q, k, attnL);
        softmax_kernel<<<BB*HH*TT, 256>>>(attnL);
        av_kernel<<<gAV, thr>>>(attnL, v, o);

        sgemm_kernel<false,true,false><<<gC, thr>>>(o, CC, Wo + (size_t)l*CC*CC, CC,
                                                    bo + l*CC, h, CC, h, CC, CC, CC);

        ln_kernel<<<NTOK, 256>>>(h, ln3g + l*CC, ln3b + l*CC, hn);

        // ff = relu(hn @ W1 + b1), stored with padded ld = FFP
        sgemm_kernel<true,false,true><<<gF1, thr>>>(hn, CC, W1 + (size_t)l*CC*FFD, FFD,
                                                    b1 + l*FFD, nullptr, 0, ff, FFP, FFD, CC);
        // h = h + ff @ W2 + b2   (K = FFD = 100, A lda = FFP for alignment)
        sgemm_kernel<false,true,false><<<gC, thr>>>(ff, FFP, W2 + (size_t)l*FFD*CC, CC,
                                                    b2 + l*CC, h, CC, h, CC, CC, FFD);
    }

    ln_kernel<<<NTOK, 256>>>(h, lnfg, lnfb, hn);
    sgemm_kernel<false,false,false><<<gL, thr>>>(hn, CC, Wout, VV,
                                                 bout, nullptr, 0, out_logits, VV, VV, CC);
}

// round 5
// speedup vs baseline: 6.8667x; 2.7669x over previous
#include <cuda_runtime.h>
#include <math.h>
#include <stdint.h>

#define BB 2
#define TT 1024
#define CC 1024
#define HH 8
#define HD 128
#define LL 4
#define FFD 100
#define FFP 128
#define VV 32000
#define NTOK (BB*TT)
#define SCALE 0.08838834764831845f
#define LN_EPS 1e-5f

#define TMM 64      /* tile M */
#define TNN 128     /* tile N */
#define KC  32      /* K chunk */
#define BSTRIDE 136 /* [k][n] smem row stride */

// ---------------- scratch ----------------
__device__ float g_h [NTOK*CC];
__device__ float g_hn[NTOK*CC];
__device__ float g_q [NTOK*CC];
__device__ float g_k [NTOK*CC];
__device__ float g_v [NTOK*CC];
__device__ float g_o [NTOK*CC];
__device__ float g_ff[NTOK*FFP];

// ---------------- tf32 helpers ----------------
__device__ __forceinline__ uint32_t f2tf(float f) {
    uint32_t r; asm("cvt.rna.tf32.f32 %0, %1;" : "=r"(r) : "f"(f)); return r;
}
__device__ __forceinline__ void mma_tf32(float c[4], uint32_t a0, uint32_t a1,
                                         uint32_t a2, uint32_t a3,
                                         uint32_t b0, uint32_t b1) {
    asm("mma.sync.aligned.m16n8k8.row.col.f32.tf32.tf32.f32 "
        "{%0,%1,%2,%3}, {%4,%5,%6,%7}, {%8,%9}, {%0,%1,%2,%3};"
        : "+f"(c[0]), "+f"(c[1]), "+f"(c[2]), "+f"(c[3])
        : "r"(a0), "r"(a1), "r"(a2), "r"(a3), "r"(b0), "r"(b1));
}

// ---------------- smem fill: row-major source -> XOR-swizzled [rows][32] ----------------
// src must be pre-offset to the tile's first row. k-chunk at kb.
template<int ROWS, bool KG>
__device__ __forceinline__ void ldg_rs(float4* reg, const float* __restrict__ src,
                                       int ld, int kb, int K)
{
    int t = threadIdx.x;
    #pragma unroll
    for (int i = 0; i < ROWS/32; i++) {
        int m = i*32 + (t >> 3);
        int k = kb + (t & 7)*4;
        if (!KG || k < K) reg[i] = *(const float4*)&src[(size_t)m*ld + k];
        else              reg[i] = make_float4(0.f,0.f,0.f,0.f);
    }
}
template<int ROWS>
__device__ __forceinline__ void sts_rs(uint32_t* sm, const float4* reg)
{
    int t = threadIdx.x;
    #pragma unroll
    for (int i = 0; i < ROWS/32; i++) {
        int m = i*32 + (t >> 3);
        int k4 = t & 7;
        uint32_t* p = &sm[m*32 + ((k4 ^ (m & 7)) << 2)];
        p[0] = f2tf(reg[i].x); p[1] = f2tf(reg[i].y);
        p[2] = f2tf(reg[i].z); p[3] = f2tf(reg[i].w);
    }
}

// ---------------- smem fill: [k][n] source -> [k][BSTRIDE] smem ----------------
template<bool NG, bool KG>
__device__ __forceinline__ void ldg_kn(float4* reg, const float* __restrict__ src,
                                       int ldb, int kb, int n0, int N, int K)
{
    int t = threadIdx.x;
    #pragma unroll
    for (int i = 0; i < 4; i++) {
        int r = i*8 + (t >> 5);
        int c = (t & 31)*4;
        bool ok = (!KG || (kb + r) < K) && (!NG || (n0 + c) < N);
        if (ok) reg[i] = *(const float4*)&src[(size_t)(kb+r)*ldb + n0 + c];
        else    reg[i] = make_float4(0.f,0.f,0.f,0.f);
    }
}
__device__ __forceinline__ void sts_kn(uint32_t* sm, const float4* reg)
{
    int t = threadIdx.x;
    #pragma unroll
    for (int i = 0; i < 4; i++) {
        int r = i*8 + (t >> 5);
        int c = (t & 31)*4;
        uint32_t* p = &sm[r*BSTRIDE + c];
        p[0] = f2tf(reg[i].x); p[1] = f2tf(reg[i].y);
        p[2] = f2tf(reg[i].z); p[3] = f2tf(reg[i].w);
    }
}

// ---------------- MMA over one KC chunk ----------------
// acc[i][j][4]: i = m-subtile (2 x 16), j = n-subtile (4 x 8). warp tile 32x32.
__device__ __forceinline__ void mma_chunk_kn(const uint32_t* smA, const uint32_t* smB,
                                             float acc[2][4][4],
                                             int warp_m, int warp_n, int lr, int lc)
{
    #pragma unroll
    for (int ks = 0; ks < 4; ks++) {
        int kb = ks*8, kb4 = ks*2;
        int swz = ((kb4 ^ lr) << 2) + lc;
        uint32_t b[4][2];
        #pragma unroll
        for (int j = 0; j < 4; j++) {
            int n = warp_n + j*8 + lr;
            b[j][0] = smB[(kb + lc)*BSTRIDE + n];
            b[j][1] = smB[(kb + 4 + lc)*BSTRIDE + n];
        }
        #pragma unroll
        for (int i = 0; i < 2; i++) {
            int mb = warp_m + i*16;
            uint32_t a0 = smA[(mb + lr)*32 + swz];
            uint32_t a1 = smA[(mb + 8 + lr)*32 + swz];
            uint32_t a2 = smA[(mb + lr)*32 + (swz ^ 4)];
            uint32_t a3 = smA[(mb + 8 + lr)*32 + (swz ^ 4)];
            #pragma unroll
            for (int j = 0; j < 4; j++)
                mma_tf32(acc[i][j], a0, a1, a2, a3, b[j][0], b[j][1]);
        }
    }
}
__device__ __forceinline__ void mma_chunk_rs(const uint32_t* smA, const uint32_t* smB,
                                             float acc[2][4][4],
                                             int warp_m, int warp_n, int lr, int lc)
{
    #pragma unroll
    for (int ks = 0; ks < 4; ks++) {
        int kb4 = ks*2;
        int swz = ((kb4 ^ lr) << 2) + lc;
        uint32_t b[4][2];
        #pragma unroll
        for (int j = 0; j < 4; j++) {
            int n = warp_n + j*8 + lr;
            b[j][0] = smB[n*32 + swz];
            b[j][1] = smB[n*32 + (swz ^ 4)];
        }
        #pragma unroll
        for (int i = 0; i < 2; i++) {
            int mb = warp_m + i*16;
            uint32_t a0 = smA[(mb + lr)*32 + swz];
            uint32_t a1 = smA[(mb + 8 + lr)*32 + swz];
            uint32_t a2 = smA[(mb + lr)*32 + (swz ^ 4)];
            uint32_t a3 = smA[(mb + 8 + lr)*32 + (swz ^ 4)];
            #pragma unroll
            for (int j = 0; j < 4; j++)
                mma_tf32(acc[i][j], a0, a1, a2, a3, b[j][0], b[j][1]);
        }
    }
}

// ---------------- dense GEMM (tensor core): C = A[MxK]*B[KxN] (+bias)(+add)(relu) ----------------
template<bool RELU, bool ADD, bool NG, bool KG>
__global__ __launch_bounds__(256)
void sgemm_tc(const float* __restrict__ A, int lda,
              const float* __restrict__ B, int ldb,
              const float* __restrict__ bias,
              const float* __restrict__ addp, int ldadd,
              float* __restrict__ C, int ldc,
              int N, int K)
{
    __shared__ uint32_t smA[TMM*32];
    __shared__ uint32_t smB[KC*BSTRIDE];
    int t = threadIdx.x, wid = t >> 5, lane = t & 31;
    int lr = lane >> 2, lc = lane & 3;
    int warp_m = (wid & 1)*32, warp_n = (wid >> 1)*32;
    int m0 = blockIdx.y * TMM, n0 = blockIdx.x * TNN;

    float acc[2][4][4] = {};
    float4 rA[2], rB[4];
    const float* Ap = A + (size_t)m0*lda;

    int nch = (K + KC - 1)/KC;
    ldg_rs<TMM,KG>(rA, Ap, lda, 0, K);
    ldg_kn<NG,KG>(rB, B, ldb, 0, n0, N, K);

    for (int c = 0; c < nch; c++) {
        sts_rs<TMM>(smA, rA);
        sts_kn(smB, rB);
        __syncthreads();
        if (c + 1 < nch) {
            ldg_rs<TMM,KG>(rA, Ap, lda, (c+1)*KC, K);
            ldg_kn<NG,KG>(rB, B, ldb, (c+1)*KC, n0, N, K);
        }
        mma_chunk_kn(smA, smB, acc, warp_m, warp_n, lr, lc);
        __syncthreads();
    }

    #pragma unroll
    for (int i = 0; i < 2; i++) {
        int r0 = m0 + warp_m + i*16 + lr;
        #pragma unroll
        for (int j = 0; j < 4; j++) {
            int cg = n0 + warp_n + j*8 + 2*lc;
            if (NG && cg >= N) continue;
            float2 bb = *(const float2*)&bias[cg];
            float v0 = acc[i][j][0] + bb.x, v1 = acc[i][j][1] + bb.y;
            float v2 = acc[i][j][2] + bb.x, v3 = acc[i][j][3] + bb.y;
            if (ADD) {
                float2 p0 = *(const float2*)&addp[(size_t)r0*ldadd + cg];
                float2 p1 = *(const float2*)&addp[(size_t)(r0+8)*ldadd + cg];
                v0 += p0.x; v1 += p0.y; v2 += p1.x; v3 += p1.y;
            }
            if (RELU) {
                v0 = fmaxf(v0,0.f); v1 = fmaxf(v1,0.f);
                v2 = fmaxf(v2,0.f); v3 = fmaxf(v3,0.f);
            }
            *(float2*)&C[(size_t)r0*ldc + cg]     = make_float2(v0, v1);
            *(float2*)&C[(size_t)(r0+8)*ldc + cg] = make_float2(v2, v3);
        }
    }
}

// ---------------- scores (tensor core): S = Q K^T * scale + alibi; 0 above diag ----------------
__global__ __launch_bounds__(256)
void scores_tc(const float* __restrict__ Q, const float* __restrict__ Kc,
               float* __restrict__ attn)
{
    int zb = blockIdx.z, b = zb >> 3, h = zb & 7;
    int m0 = blockIdx.y * TMM, n0 = blockIdx.x * TNN;
    int t = threadIdx.x;
    float* S = attn + (size_t)zb*TT*TT;

    if (n0 > m0 + (TMM-1)) {      // fully masked tile -> zeros
        int base = t*4;           // 256 threads x 4 floats x 32 iters? rows=64,cols=128
        #pragma unroll
        for (int it = 0; it < 8; it++) {
            int e = base + it*1024;          // 8192 floats total
            int r = e >> 7, cidx = e & 127;
            *(float4*)&S[(size_t)(m0+r)*TT + n0 + cidx] = make_float4(0.f,0.f,0.f,0.f);
        }
        return;
    }

    __shared__ uint32_t smA[TMM*32];
    __shared__ uint32_t smB[TNN*32];
    int wid = t >> 5, lane = t & 31;
    int lr = lane >> 2, lc = lane & 3;
    int warp_m = (wid & 1)*32, warp_n = (wid >> 1)*32;

    const float* Aq = Q  + (size_t)b*TT*CC + h*HD + (size_t)m0*CC;
    const float* Ak = Kc + (size_t)b*TT*CC + h*HD + (size_t)n0*CC;

    float acc[2][4][4] = {};
    float4 rA[2], rB[4];
    ldg_rs<TMM,false>(rA, Aq, CC, 0, HD);
    ldg_rs<TNN,false>(rB, Ak, CC, 0, HD);

    #pragma unroll
    for (int c = 0; c < HD/KC; c++) {
        sts_rs<TMM>(smA, rA);
        sts_rs<TNN>(smB, rB);
        __syncthreads();
        if (c + 1 < HD/KC) {
            ldg_rs<TMM,false>(rA, Aq, CC, (c+1)*KC, HD);
            ldg_rs<TNN,false>(rB, Ak, CC, (c+1)*KC, HD);
        }
        mma_chunk_rs(smA, smB, acc, warp_m, warp_n, lr, lc);
        __syncthreads();
    }

    float slope = exp2f(-(float)(h+1));
    #pragma unroll
    for (int i = 0; i < 2; i++) {
        int r0 = m0 + warp_m + i*16 + lr;
        #pragma unroll
        for (int j = 0; j < 4; j++) {
            int cg = n0 + warp_n + j*8 + 2*lc;
            float v0 = (cg   <= r0  ) ? acc[i][j][0]*SCALE + slope*(float)(cg  -r0  ) : 0.f;
            float v1 = (cg+1 <= r0  ) ? acc[i][j][1]*SCALE + slope*(float)(cg+1-r0  ) : 0.f;
            float v2 = (cg   <= r0+8) ? acc[i][j][2]*SCALE + slope*(float)(cg  -r0-8) : 0.f;
            float v3 = (cg+1 <= r0+8) ? acc[i][j][3]*SCALE + slope*(float)(cg+1-r0-8) : 0.f;
            *(float2*)&S[(size_t)r0*TT + cg]     = make_float2(v0, v1);
            *(float2*)&S[(size_t)(r0+8)*TT + cg] = make_float2(v2, v3);
        }
    }
}

// ---------------- softmax over causal prefix ----------------
__global__ void softmax_kernel(float* __restrict__ attnL)
{
    int rowid = blockIdx.x;
    int i = rowid & (TT-1);
    int L = i + 1;
    float* r = attnL + (size_t)rowid * TT;
    __shared__ float red[256];
    int tid = threadIdx.x;

    float m = -INFINITY;
    for (int c = tid; c < L; c += 256) m = fmaxf(m, r[c]);
    red[tid] = m; __syncthreads();
    for (int q = 128; q > 0; q >>= 1) { if (tid < q) red[tid] = fmaxf(red[tid], red[tid+q]); __syncthreads(); }
    m = red[0]; __syncthreads();

    float s = 0.f;
    for (int c = tid; c < L; c += 256) { float e = __expf(r[c]-m); r[c] = e; s += e; }
    red[tid] = s; __syncthreads();
    for (int q = 128; q > 0; q >>= 1) { if (tid < q) red[tid] += red[tid+q]; __syncthreads(); }
    float inv = 1.f / red[0];

    for (int c = tid; c < L; c += 256) r[c] *= inv;
}

// ---------------- O = attn @ V (tensor core), causal k-bound ----------------
__global__ __launch_bounds__(256)
void av_tc(const float* __restrict__ attn, const float* __restrict__ V,
           float* __restrict__ O)
{
    int zb = blockIdx.z, b = zb >> 3, h = zb & 7;
    int m0 = blockIdx.y * TMM;
    int t = threadIdx.x, wid = t >> 5, lane = t & 31;
    int lr = lane >> 2, lc = lane & 3;
    int warp_m = (wid & 1)*32, warp_n = (wid >> 1)*32;

    const float* A  = attn + (size_t)zb*TT*TT + (size_t)m0*TT;
    const float* Bv = V + (size_t)b*TT*CC + h*HD;
    float*       Co = O + (size_t)b*TT*CC + h*HD;

    __shared__ uint32_t smA[TMM*32];
    __shared__ uint32_t smB[KC*BSTRIDE];

    float acc[2][4][4] = {};
    float4 rA[2], rB[4];
    int nch = (m0 + TMM)/KC;

    ldg_rs<TMM,false>(rA, A, TT, 0, TT);
    ldg_kn<false,false>(rB, Bv, CC, 0, 0, HD, TT);

    for (int c = 0; c < nch; c++) {
        sts_rs<TMM>(smA, rA);
        sts_kn(smB, rB);
        __syncthreads();
        if (c + 1 < nch) {
            ldg_rs<TMM,false>(rA, A, TT, (c+1)*KC, TT);
            ldg_kn<false,false>(rB, Bv, CC, (c+1)*KC, 0, HD, TT);
        }
        mma_chunk_kn(smA, smB, acc, warp_m, warp_n, lr, lc);
        __syncthreads();
    }

    #pragma unroll
    for (int i = 0; i < 2; i++) {
        int r0 = m0 + warp_m + i*16 + lr;
        #pragma unroll
        for (int j = 0; j < 4; j++) {
            int cg = warp_n + j*8 + 2*lc;
            *(float2*)&Co[(size_t)r0*CC + cg]     = make_float2(acc[i][j][0], acc[i][j][1]);
            *(float2*)&Co[(size_t)(r0+8)*CC + cg] = make_float2(acc[i][j][2], acc[i][j][3]);
        }
    }
}

// ---------------- embedding / layernorm ----------------
__global__ void embed_kernel(const int* __restrict__ x, const float* __restrict__ emb,
                             float* __restrict__ h)
{
    int idx = blockIdx.x * 256 + threadIdx.x;
    int n = idx >> 8, c = idx & 255;
    ((float4*)h)[idx] = ((const float4*)emb)[(size_t)x[n]*(CC/4) + c];
}

__global__ void ln_kernel(const float* __restrict__ in, const float* __restrict__ g,
                          const float* __restrict__ b, float* __restrict__ out)
{
    int row = blockIdx.x, tid = threadIdx.x;
    const float4* xr = (const float4*)(in + (size_t)row*CC);
    float4 x = xr[tid];
    __shared__ float red[32];

    float s = x.x + x.y + x.z + x.w;
    #pragma unroll
    for (int o = 16; o; o >>= 1) s += __shfl_xor_sync(0xffffffffu, s, o);
    if ((tid & 31) == 0) red[tid >> 5] = s;
    __syncthreads();
    if (tid == 0) {
        float tsum = 0.f;
        #pragma unroll
        for (int w = 0; w < 8; w++) tsum += red[w];
        red[0] = tsum;
    }
    __syncthreads();
    float mu = red[0] * (1.f/CC);
    __syncthreads();

    float4 d = make_float4(x.x-mu, x.y-mu, x.z-mu, x.w-mu);
    float v = d.x*d.x + d.y*d.y + d.z*d.z + d.w*d.w;
    #pragma unroll
    for (int o = 16; o; o >>= 1) v += __shfl_xor_sync(0xffffffffu, v, o);
    if ((tid & 31) == 0) red[tid >> 5] = v;
    __syncthreads();
    if (tid == 0) {
        float tsum = 0.f;
        #pragma unroll
        for (int w = 0; w < 8; w++) tsum += red[w];
        red[0] = tsum;
    }
    __syncthreads();
    float rstd = rsqrtf(red[0] * (1.f/CC) + LN_EPS);

    float4 gg = ((const float4*)g)[tid];
    float4 bb = ((const float4*)b)[tid];
    float4 o4;
    o4.x = d.x*rstd*gg.x + bb.x;
    o4.y = d.y*rstd*gg.y + bb.y;
    o4.z = d.z*rstd*gg.z + bb.z;
    o4.w = d.w*rstd*gg.w + bb.w;
    ((float4*)(out + (size_t)row*CC))[tid] = o4;
}

// ---------------- host ----------------
extern "C" void kernel_launch(void* const* d_in, const int* in_sizes, int n_in,
                              void* d_out, int out_size)
{
    const int*   x    = (const int*)  d_in[0];
    const float* emb  = (const float*)d_in[1];
    const float* Wq   = (const float*)d_in[2];
    const float* bq   = (const float*)d_in[3];
    const float* Wk   = (const float*)d_in[4];
    const float* bk   = (const float*)d_in[5];
    const float* Wv   = (const float*)d_in[6];
    const float* bv   = (const float*)d_in[7];
    const float* Wo   = (const float*)d_in[8];
    const float* bo   = (const float*)d_in[9];
    const float* W1   = (const float*)d_in[10];
    const float* b1   = (const float*)d_in[11];
    const float* W2   = (const float*)d_in[12];
    const float* b2   = (const float*)d_in[13];
    const float* ln1g = (const float*)d_in[14];
    const float* ln1b = (const float*)d_in[15];
    const float* ln3g = (const float*)d_in[16];
    const float* ln3b = (const float*)d_in[17];
    const float* lnfg = (const float*)d_in[18];
    const float* lnfb = (const float*)d_in[19];
    const float* Wout = (const float*)d_in[20];
    const float* bout = (const float*)d_in[21];

    float* out_logits = (float*)d_out;                   // [B,T,V]
    float* out_attn   = out_logits + (size_t)BB*TT*VV;   // [L,B,H,T,T]

    float *h, *hn, *q, *k, *v, *o, *ff;
    cudaGetSymbolAddress((void**)&h,  g_h);
    cudaGetSymbolAddress((void**)&hn, g_hn);
    cudaGetSymbolAddress((void**)&q,  g_q);
    cudaGetSymbolAddress((void**)&k,  g_k);
    cudaGetSymbolAddress((void**)&v,  g_v);
    cudaGetSymbolAddress((void**)&o,  g_o);
    cudaGetSymbolAddress((void**)&ff, g_ff);

    embed_kernel<<<NTOK, 256>>>(x, emb, h);

    dim3 thr(256);
    dim3 gC(CC/TNN, NTOK/TMM);          // 8 x 32
    dim3 gS(TT/TNN, TT/TMM, BB*HH);     // 8 x 16 x 16
    dim3 gAV(1, TT/TMM, BB*HH);         // 1 x 16 x 16
    dim3 gF1(1, NTOK/TMM);              // N=100 -> 1 tile
    dim3 gL(VV/TNN, NTOK/TMM);          // 250 x 32

    for (int l = 0; l < LL; l++) {
        float* attnL = out_attn + (size_t)l*BB*HH*TT*TT;

        ln_kernel<<<NTOK, 256>>>(h, ln1g + l*CC, ln1b + l*CC, hn);

        sgemm_tc<false,false,false,false><<<gC, thr>>>(hn, CC, Wq + (size_t)l*CC*CC, CC,
                                                       bq + l*CC, nullptr, 0, q, CC, CC, CC);
        sgemm_tc<false,false,false,false><<<gC, thr>>>(hn, CC, Wk + (size_t)l*CC*CC, CC,
                                                       bk + l*CC, nullptr, 0, k, CC, CC, CC);
        sgemm_tc<false,false,false,false><<<gC, thr>>>(hn, CC, Wv + (size_t)l*CC*CC, CC,
                                                       bv + l*CC, nullptr, 0, v, CC, CC, CC);

        scores_tc<<<gS, thr>>>(q, k, attnL);
        softmax_kernel<<<BB*HH*TT, 256>>>(attnL);
        av_tc<<<gAV, thr>>>(attnL, v, o);

        sgemm_tc<false,true,false,false><<<gC, thr>>>(o, CC, Wo + (size_t)l*CC*CC, CC,
                                                      bo + l*CC, h, CC, h, CC, CC, CC);

        ln_kernel<<<NTOK, 256>>>(h, ln3g + l*CC, ln3b + l*CC, hn);

        // ff = relu(hn @ W1 + b1): N=100 guarded, stored with ld = FFP(128)
        sgemm_tc<true,false,true,false><<<gF1, thr>>>(hn, CC, W1 + (size_t)l*CC*FFD, FFD,
                                                      b1 + l*FFD, nullptr, 0, ff, FFP, FFD, CC);
        // h = h + ff @ W2 + b2: K=100 guarded (ff lda=FFP, cols >=100 zeroed via guard)
        sgemm_tc<false,true,false,true><<<gC, thr>>>(ff, FFP, W2 + (size_t)l*FFD*CC, CC,
                                                     b2 + l*CC, h, CC, h, CC, CC, FFD);
    }

    ln_kernel<<<NTOK, 256>>>(h, lnfg, lnfb, hn);
    sgemm_tc<false,false,false,false><<<gL, thr>>>(hn, CC, Wout, VV,
                                                   bout, nullptr, 0, out_logits, VV, VV, CC);
}

// round 6
// speedup vs baseline: 6.9089x; 1.0061x over previous
#include <cuda_runtime.h>
#include <math.h>
#include <stdint.h>

#define BB 2
#define TT 1024
#define CC 1024
#define HH 8
#define HD 128
#define LL 4
#define FFD 100
#define FFP 128
#define VV 32000
#define NTOK (BB*TT)
#define SCALE 0.08838834764831845f
#define LN_EPS 1e-5f

#define TMM 64      /* attn tile M */
#define TNN 128     /* attn tile N */
#define KC  32      /* K chunk */
#define BSTRIDE 136 /* [k][n] smem row stride */

#define GM 128      /* dense gemm tile M */
#define GN 128      /* dense gemm tile N */
#define AW (GM*32)          /* A stage words */
#define BW (KC*BSTRIDE)     /* B stage words */
#define GSMEM ((AW + BW) * 2 * 4)   /* bytes, double-buffered */

// ---------------- scratch ----------------
__device__ float g_h [NTOK*CC];
__device__ float g_hn[NTOK*CC];
__device__ float g_q [NTOK*CC];
__device__ float g_k [NTOK*CC];
__device__ float g_v [NTOK*CC];
__device__ float g_o [NTOK*CC];
__device__ float g_ff[NTOK*FFP];

// ---------------- tf32 helpers ----------------
__device__ __forceinline__ uint32_t f2tf(float f) {
    uint32_t r; asm("cvt.rna.tf32.f32 %0, %1;" : "=r"(r) : "f"(f)); return r;
}
__device__ __forceinline__ void mma_tf32(float c[4], uint32_t a0, uint32_t a1,
                                         uint32_t a2, uint32_t a3,
                                         uint32_t b0, uint32_t b1) {
    asm("mma.sync.aligned.m16n8k8.row.col.f32.tf32.tf32.f32 "
        "{%0,%1,%2,%3}, {%4,%5,%6,%7}, {%8,%9}, {%0,%1,%2,%3};"
        : "+f"(c[0]), "+f"(c[1]), "+f"(c[2]), "+f"(c[3])
        : "r"(a0), "r"(a1), "r"(a2), "r"(a3), "r"(b0), "r"(b1));
}

// ---------------- smem fill: row-major source -> XOR-swizzled [rows][32] ----------------
template<int ROWS, bool KG>
__device__ __forceinline__ void ldg_rs(float4* reg, const float* __restrict__ src,
                                       int ld, int kb, int K)
{
    int t = threadIdx.x;
    #pragma unroll
    for (int i = 0; i < ROWS/32; i++) {
        int m = i*32 + (t >> 3);
        int k = kb + (t & 7)*4;
        if (!KG || k < K) reg[i] = *(const float4*)&src[(size_t)m*ld + k];
        else              reg[i] = make_float4(0.f,0.f,0.f,0.f);
    }
}
template<int ROWS>
__device__ __forceinline__ void sts_rs(uint32_t* sm, const float4* reg)
{
    int t = threadIdx.x;
    #pragma unroll
    for (int i = 0; i < ROWS/32; i++) {
        int m = i*32 + (t >> 3);
        int k4 = t & 7;
        uint32_t* p = &sm[m*32 + ((k4 ^ (m & 7)) << 2)];
        p[0] = f2tf(reg[i].x); p[1] = f2tf(reg[i].y);
        p[2] = f2tf(reg[i].z); p[3] = f2tf(reg[i].w);
    }
}

// ---------------- smem fill: [k][n] source -> [k][BSTRIDE] smem ----------------
template<bool NG, bool KG>
__device__ __forceinline__ void ldg_kn(float4* reg, const float* __restrict__ src,
                                       int ldb, int kb, int n0, int N, int K)
{
    int t = threadIdx.x;
    #pragma unroll
    for (int i = 0; i < 4; i++) {
        int r = i*8 + (t >> 5);
        int c = (t & 31)*4;
        bool ok = (!KG || (kb + r) < K) && (!NG || (n0 + c) < N);
        if (ok) reg[i] = *(const float4*)&src[(size_t)(kb+r)*ldb + n0 + c];
        else    reg[i] = make_float4(0.f,0.f,0.f,0.f);
    }
}
__device__ __forceinline__ void sts_kn(uint32_t* sm, const float4* reg)
{
    int t = threadIdx.x;
    #pragma unroll
    for (int i = 0; i < 4; i++) {
        int r = i*8 + (t >> 5);
        int c = (t & 31)*4;
        uint32_t* p = &sm[r*BSTRIDE + c];
        p[0] = f2tf(reg[i].x); p[1] = f2tf(reg[i].y);
        p[2] = f2tf(reg[i].z); p[3] = f2tf(reg[i].w);
    }
}

// ---------------- MMA chunk, attn kernels: warp tile 32x32 ----------------
__device__ __forceinline__ void mma_chunk_kn(const uint32_t* smA, const uint32_t* smB,
                                             float acc[2][4][4],
                                             int warp_m, int warp_n, int lr, int lc)
{
    #pragma unroll
    for (int ks = 0; ks < 4; ks++) {
        int kb = ks*8, kb4 = ks*2;
        int swz = ((kb4 ^ lr) << 2) + lc;
        uint32_t b[4][2];
        #pragma unroll
        for (int j = 0; j < 4; j++) {
            int n = warp_n + j*8 + lr;
            b[j][0] = smB[(kb + lc)*BSTRIDE + n];
            b[j][1] = smB[(kb + 4 + lc)*BSTRIDE + n];
        }
        #pragma unroll
        for (int i = 0; i < 2; i++) {
            int mb = warp_m + i*16;
            uint32_t a0 = smA[(mb + lr)*32 + swz];
            uint32_t a1 = smA[(mb + 8 + lr)*32 + swz];
            uint32_t a2 = smA[(mb + lr)*32 + (swz ^ 4)];
            uint32_t a3 = smA[(mb + 8 + lr)*32 + (swz ^ 4)];
            #pragma unroll
            for (int j = 0; j < 4; j++)
                mma_tf32(acc[i][j], a0, a1, a2, a3, b[j][0], b[j][1]);
        }
    }
}
__device__ __forceinline__ void mma_chunk_rs(const uint32_t* smA, const uint32_t* smB,
                                             float acc[2][4][4],
                                             int warp_m, int warp_n, int lr, int lc)
{
    #pragma unroll
    for (int ks = 0; ks < 4; ks++) {
        int kb4 = ks*2;
        int swz = ((kb4 ^ lr) << 2) + lc;
        uint32_t b[4][2];
        #pragma unroll
        for (int j = 0; j < 4; j++) {
            int n = warp_n + j*8 + lr;
            b[j][0] = smB[n*32 + swz];
            b[j][1] = smB[n*32 + (swz ^ 4)];
        }
        #pragma unroll
        for (int i = 0; i < 2; i++) {
            int mb = warp_m + i*16;
            uint32_t a0 = smA[(mb + lr)*32 + swz];
            uint32_t a1 = smA[(mb + 8 + lr)*32 + swz];
            uint32_t a2 = smA[(mb + lr)*32 + (swz ^ 4)];
            uint32_t a3 = smA[(mb + 8 + lr)*32 + (swz ^ 4)];
            #pragma unroll
            for (int j = 0; j < 4; j++)
                mma_tf32(acc[i][j], a0, a1, a2, a3, b[j][0], b[j][1]);
        }
    }
}

// ---------------- MMA chunk, dense gemm: warp tile 64x32 ----------------
__device__ __forceinline__ void mma_chunk128(const uint32_t* smA, const uint32_t* smB,
                                             float acc[4][4][4],
                                             int warp_m, int warp_n, int lr, int lc)
{
    #pragma unroll
    for (int ks = 0; ks < 4; ks++) {
        int kb = ks*8, kb4 = ks*2;
        int swz = ((kb4 ^ lr) << 2) + lc;
        uint32_t b[4][2];
        #pragma unroll
        for (int j = 0; j < 4; j++) {
            int n = warp_n + j*8 + lr;
            b[j][0] = smB[(kb + lc)*BSTRIDE + n];
            b[j][1] = smB[(kb + 4 + lc)*BSTRIDE + n];
        }
        #pragma unroll
        for (int i = 0; i < 4; i++) {
            int mb = warp_m + i*16;
            uint32_t a0 = smA[(mb + lr)*32 + swz];
            uint32_t a1 = smA[(mb + 8 + lr)*32 + swz];
            uint32_t a2 = smA[(mb + lr)*32 + (swz ^ 4)];
            uint32_t a3 = smA[(mb + 8 + lr)*32 + (swz ^ 4)];
            #pragma unroll
            for (int j = 0; j < 4; j++)
                mma_tf32(acc[i][j], a0, a1, a2, a3, b[j][0], b[j][1]);
        }
    }
}

// ---------------- dense GEMM 128x128x32, double-buffered, m on blockIdx.x ----------------
template<bool RELU, bool ADD, bool NG, bool KG>
__global__ __launch_bounds__(256)
void gemm128(const float* __restrict__ A, int lda,
             const float* __restrict__ B, int ldb,
             const float* __restrict__ bias,
             const float* __restrict__ addp, int ldadd,
             float* __restrict__ C, int ldc,
             int N, int K)
{
    extern __shared__ uint32_t sm[];
    uint32_t* smA = sm;            // [2][GM*32]
    uint32_t* smB = sm + 2*AW;     // [2][KC*BSTRIDE]
    int t = threadIdx.x, wid = t >> 5, lane = t & 31;
    int lr = lane >> 2, lc = lane & 3;
    int warp_m = (wid & 1)*64, warp_n = (wid >> 1)*32;
    int m0 = blockIdx.x * GM, n0 = blockIdx.y * GN;

    float acc[4][4][4] = {};
    float4 rA[4], rB[4];
    const float* Ap = A + (size_t)m0*lda;
    int nch = (K + KC - 1)/KC;

    ldg_rs<GM,KG>(rA, Ap, lda, 0, K);
    ldg_kn<NG,KG>(rB, B, ldb, 0, n0, N, K);
    sts_rs<GM>(smA, rA);
    sts_kn(smB, rB);
    __syncthreads();

    for (int c = 0; c < nch; c++) {
        int cur = c & 1;
        if (c + 1 < nch) {
            ldg_rs<GM,KG>(rA, Ap, lda, (c+1)*KC, K);
            ldg_kn<NG,KG>(rB, B, ldb, (c+1)*KC, n0, N, K);
        }
        mma_chunk128(smA + cur*AW, smB + cur*BW, acc, warp_m, warp_n, lr, lc);
        if (c + 1 < nch) {
            int nxt = (c+1) & 1;
            sts_rs<GM>(smA + nxt*AW, rA);
            sts_kn(smB + nxt*BW, rB);
            __syncthreads();
        }
    }

    #pragma unroll
    for (int i = 0; i < 4; i++) {
        int r0 = m0 + warp_m + i*16 + lr;
        #pragma unroll
        for (int j = 0; j < 4; j++) {
            int cg = n0 + warp_n + j*8 + 2*lc;
            if (NG && cg >= N) continue;
            float2 bb = *(const float2*)&bias[cg];
            float v0 = acc[i][j][0] + bb.x, v1 = acc[i][j][1] + bb.y;
            float v2 = acc[i][j][2] + bb.x, v3 = acc[i][j][3] + bb.y;
            if (ADD) {
                float2 p0 = *(const float2*)&addp[(size_t)r0*ldadd + cg];
                float2 p1 = *(const float2*)&addp[(size_t)(r0+8)*ldadd + cg];
                v0 += p0.x; v1 += p0.y; v2 += p1.x; v3 += p1.y;
            }
            if (RELU) {
                v0 = fmaxf(v0,0.f); v1 = fmaxf(v1,0.f);
                v2 = fmaxf(v2,0.f); v3 = fmaxf(v3,0.f);
            }
            *(float2*)&C[(size_t)r0*ldc + cg]     = make_float2(v0, v1);
            *(float2*)&C[(size_t)(r0+8)*ldc + cg] = make_float2(v2, v3);
        }
    }
}

// ---------------- scores: S = Q K^T * scale + alibi; 0 above diag ----------------
__global__ __launch_bounds__(256)
void scores_tc(const float* __restrict__ Q, const float* __restrict__ Kc,
               float* __restrict__ attn)
{
    int zb = blockIdx.z, b = zb >> 3, h = zb & 7;
    int m0 = blockIdx.y * TMM, n0 = blockIdx.x * TNN;
    int t = threadIdx.x;
    float* S = attn + (size_t)zb*TT*TT;

    if (n0 > m0 + (TMM-1)) {
        int base = t*4;
        #pragma unroll
        for (int it = 0; it < 8; it++) {
            int e = base + it*1024;
            int r = e >> 7, cidx = e & 127;
            *(float4*)&S[(size_t)(m0+r)*TT + n0 + cidx] = make_float4(0.f,0.f,0.f,0.f);
        }
        return;
    }

    __shared__ uint32_t smA[TMM*32];
    __shared__ uint32_t smB[TNN*32];
    int wid = t >> 5, lane = t & 31;
    int lr = lane >> 2, lc = lane & 3;
    int warp_m = (wid & 1)*32, warp_n = (wid >> 1)*32;

    const float* Aq = Q  + (size_t)b*TT*CC + h*HD + (size_t)m0*CC;
    const float* Ak = Kc + (size_t)b*TT*CC + h*HD + (size_t)n0*CC;

    float acc[2][4][4] = {};
    float4 rA[2], rB[4];
    ldg_rs<TMM,false>(rA, Aq, CC, 0, HD);
    ldg_rs<TNN,false>(rB, Ak, CC, 0, HD);

    #pragma unroll
    for (int c = 0; c < HD/KC; c++) {
        sts_rs<TMM>(smA, rA);
        sts_rs<TNN>(smB, rB);
        __syncthreads();
        if (c + 1 < HD/KC) {
            ldg_rs<TMM,false>(rA, Aq, CC, (c+1)*KC, HD);
            ldg_rs<TNN,false>(rB, Ak, CC, (c+1)*KC, HD);
        }
        mma_chunk_rs(smA, smB, acc, warp_m, warp_n, lr, lc);
        __syncthreads();
    }

    float slope = exp2f(-(float)(h+1));
    #pragma unroll
    for (int i = 0; i < 2; i++) {
        int r0 = m0 + warp_m + i*16 + lr;
        #pragma unroll
        for (int j = 0; j < 4; j++) {
            int cg = n0 + warp_n + j*8 + 2*lc;
            float v0 = (cg   <= r0  ) ? acc[i][j][0]*SCALE + slope*(float)(cg  -r0  ) : 0.f;
            float v1 = (cg+1 <= r0  ) ? acc[i][j][1]*SCALE + slope*(float)(cg+1-r0  ) : 0.f;
            float v2 = (cg   <= r0+8) ? acc[i][j][2]*SCALE + slope*(float)(cg  -r0-8) : 0.f;
            float v3 = (cg+1 <= r0+8) ? acc[i][j][3]*SCALE + slope*(float)(cg+1-r0-8) : 0.f;
            *(float2*)&S[(size_t)r0*TT + cg]     = make_float2(v0, v1);
            *(float2*)&S[(size_t)(r0+8)*TT + cg] = make_float2(v2, v3);
        }
    }
}

// ---------------- softmax over causal prefix ----------------
__global__ void softmax_kernel(float* __restrict__ attnL)
{
    int rowid = blockIdx.x;
    int i = rowid & (TT-1);
    int L = i + 1;
    float* r = attnL + (size_t)rowid * TT;
    __shared__ float red[256];
    int tid = threadIdx.x;

    float m = -INFINITY;
    for (int c = tid; c < L; c += 256) m = fmaxf(m, r[c]);
    red[tid] = m; __syncthreads();
    for (int q = 128; q > 0; q >>= 1) { if (tid < q) red[tid] = fmaxf(red[tid], red[tid+q]); __syncthreads(); }
    m = red[0]; __syncthreads();

    float s = 0.f;
    for (int c = tid; c < L; c += 256) { float e = __expf(r[c]-m); r[c] = e; s += e; }
    red[tid] = s; __syncthreads();
    for (int q = 128; q > 0; q >>= 1) { if (tid < q) red[tid] += red[tid+q]; __syncthreads(); }
    float inv = 1.f / red[0];

    for (int c = tid; c < L; c += 256) r[c] *= inv;
}

// ---------------- O = attn @ V, causal k-bound ----------------
__global__ __launch_bounds__(256)
void av_tc(const float* __restrict__ attn, const float* __restrict__ V,
           float* __restrict__ O)
{
    int zb = blockIdx.z, b = zb >> 3, h = zb & 7;
    int m0 = blockIdx.y * TMM;
    int t = threadIdx.x, wid = t >> 5, lane = t & 31;
    int lr = lane >> 2, lc = lane & 3;
    int warp_m = (wid & 1)*32, warp_n = (wid >> 1)*32;

    const float* A  = attn + (size_t)zb*TT*TT + (size_t)m0*TT;
    const float* Bv = V + (size_t)b*TT*CC + h*HD;
    float*       Co = O + (size_t)b*TT*CC + h*HD;

    __shared__ uint32_t smA[TMM*32];
    __shared__ uint32_t smB[KC*BSTRIDE];

    float acc[2][4][4] = {};
    float4 rA[2], rB[4];
    int nch = (m0 + TMM)/KC;

    ldg_rs<TMM,false>(rA, A, TT, 0, TT);
    ldg_kn<false,false>(rB, Bv, CC, 0, 0, HD, TT);

    for (int c = 0; c < nch; c++) {
        sts_rs<TMM>(smA, rA);
        sts_kn(smB, rB);
        __syncthreads();
        if (c + 1 < nch) {
            ldg_rs<TMM,false>(rA, A, TT, (c+1)*KC, TT);
            ldg_kn<false,false>(rB, Bv, CC, (c+1)*KC, 0, HD, TT);
        }
        mma_chunk_kn(smA, smB, acc, warp_m, warp_n, lr, lc);
        __syncthreads();
    }

    #pragma unroll
    for (int i = 0; i < 2; i++) {
        int r0 = m0 + warp_m + i*16 + lr;
        #pragma unroll
        for (int j = 0; j < 4; j++) {
            int cg = warp_n + j*8 + 2*lc;
            *(float2*)&Co[(size_t)r0*CC + cg]     = make_float2(acc[i][j][0], acc[i][j][1]);
            *(float2*)&Co[(size_t)(r0+8)*CC + cg] = make_float2(acc[i][j][2], acc[i][j][3]);
        }
    }
}

// ---------------- embedding / layernorm ----------------
__global__ void embed_kernel(const int* __restrict__ x, const float* __restrict__ emb,
                             float* __restrict__ h)
{
    int idx = blockIdx.x * 256 + threadIdx.x;
    int n = idx >> 8, c = idx & 255;
    ((float4*)h)[idx] = ((const float4*)emb)[(size_t)x[n]*(CC/4) + c];
}

__global__ void ln_kernel(const float* __restrict__ in, const float* __restrict__ g,
                          const float* __restrict__ b, float* __restrict__ out)
{
    int row = blockIdx.x, tid = threadIdx.x;
    const float4* xr = (const float4*)(in + (size_t)row*CC);
    float4 x = xr[tid];
    __shared__ float red[32];

    float s = x.x + x.y + x.z + x.w;
    #pragma unroll
    for (int o = 16; o; o >>= 1) s += __shfl_xor_sync(0xffffffffu, s, o);
    if ((tid & 31) == 0) red[tid >> 5] = s;
    __syncthreads();
    if (tid == 0) {
        float tsum = 0.f;
        #pragma unroll
        for (int w = 0; w < 8; w++) tsum += red[w];
        red[0] = tsum;
    }
    __syncthreads();
    float mu = red[0] * (1.f/CC);
    __syncthreads();

    float4 d = make_float4(x.x-mu, x.y-mu, x.z-mu, x.w-mu);
    float v = d.x*d.x + d.y*d.y + d.z*d.z + d.w*d.w;
    #pragma unroll
    for (int o = 16; o; o >>= 1) v += __shfl_xor_sync(0xffffffffu, v, o);
    if ((tid & 31) == 0) red[tid >> 5] = v;
    __syncthreads();
    if (tid == 0) {
        float tsum = 0.f;
        #pragma unroll
        for (int w = 0; w < 8; w++) tsum += red[w];
        red[0] = tsum;
    }
    __syncthreads();
    float rstd = rsqrtf(red[0] * (1.f/CC) + LN_EPS);

    float4 gg = ((const float4*)g)[tid];
    float4 bb = ((const float4*)b)[tid];
    float4 o4;
    o4.x = d.x*rstd*gg.x + bb.x;
    o4.y = d.y*rstd*gg.y + bb.y;
    o4.z = d.z*rstd*gg.z + bb.z;
    o4.w = d.w*rstd*gg.w + bb.w;
    ((float4*)(out + (size_t)row*CC))[tid] = o4;
}

// ---------------- host ----------------
extern "C" void kernel_launch(void* const* d_in, const int* in_sizes, int n_in,
                              void* d_out, int out_size)
{
    const int*   x    = (const int*)  d_in[0];
    const float* emb  = (const float*)d_in[1];
    const float* Wq   = (const float*)d_in[2];
    const float* bq   = (const float*)d_in[3];
    const float* Wk   = (const float*)d_in[4];
    const float* bk   = (const float*)d_in[5];
    const float* Wv   = (const float*)d_in[6];
    const float* bv   = (const float*)d_in[7];
    const float* Wo   = (const float*)d_in[8];
    const float* bo   = (const float*)d_in[9];
    const float* W1   = (const float*)d_in[10];
    const float* b1   = (const float*)d_in[11];
    const float* W2   = (const float*)d_in[12];
    const float* b2   = (const float*)d_in[13];
    const float* ln1g = (const float*)d_in[14];
    const float* ln1b = (const float*)d_in[15];
    const float* ln3g = (const float*)d_in[16];
    const float* ln3b = (const float*)d_in[17];
    const float* lnfg = (const float*)d_in[18];
    const float* lnfb = (const float*)d_in[19];
    const float* Wout = (const float*)d_in[20];
    const float* bout = (const float*)d_in[21];

    float* out_logits = (float*)d_out;                   // [B,T,V]
    float* out_attn   = out_logits + (size_t)BB*TT*VV;   // [L,B,H,T,T]

    float *h, *hn, *q, *k, *v, *o, *ff;
    cudaGetSymbolAddress((void**)&h,  g_h);
    cudaGetSymbolAddress((void**)&hn, g_hn);
    cudaGetSymbolAddress((void**)&q,  g_q);
    cudaGetSymbolAddress((void**)&k,  g_k);
    cudaGetSymbolAddress((void**)&v,  g_v);
    cudaGetSymbolAddress((void**)&o,  g_o);
    cudaGetSymbolAddress((void**)&ff, g_ff);

    // enlarge dynamic smem for all gemm128 instantiations used
    cudaFuncSetAttribute(gemm128<false,false,false,false>, cudaFuncAttributeMaxDynamicSharedMemorySize, GSMEM);
    cudaFuncSetAttribute(gemm128<false,true,false,false>,  cudaFuncAttributeMaxDynamicSharedMemorySize, GSMEM);
    cudaFuncSetAttribute(gemm128<true,false,true,false>,   cudaFuncAttributeMaxDynamicSharedMemorySize, GSMEM);
    cudaFuncSetAttribute(gemm128<false,true,false,true>,   cudaFuncAttributeMaxDynamicSharedMemorySize, GSMEM);

    embed_kernel<<<NTOK, 256>>>(x, emb, h);

    dim3 thr(256);
    dim3 gC(NTOK/GM, CC/GN);            // 16 x 8 (m on x)
    dim3 gS(TT/TNN, TT/TMM, BB*HH);     // 8 x 16 x 16
    dim3 gAV(1, TT/TMM, BB*HH);
    dim3 gF1(NTOK/GM, 1);
    dim3 gL(NTOK/GM, VV/GN);            // 16 x 250 (m fastest -> B-stripe L2 reuse)

    for (int l = 0; l < LL; l++) {
        float* attnL = out_attn + (size_t)l*BB*HH*TT*TT;

        ln_kernel<<<NTOK, 256>>>(h, ln1g + l*CC, ln1b + l*CC, hn);

        gemm128<false,false,false,false><<<gC, thr, GSMEM>>>(hn, CC, Wq + (size_t)l*CC*CC, CC,
                                                             bq + l*CC, nullptr, 0, q, CC, CC, CC);
        gemm128<false,false,false,false><<<gC, thr, GSMEM>>>(hn, CC, Wk + (size_t)l*CC*CC, CC,
                                                             bk + l*CC, nullptr, 0, k, CC, CC, CC);
        gemm128<false,false,false,false><<<gC, thr, GSMEM>>>(hn, CC, Wv + (size_t)l*CC*CC, CC,
                                                             bv + l*CC, nullptr, 0, v, CC, CC, CC);

        scores_tc<<<gS, thr>>>(q, k, attnL);
        softmax_kernel<<<BB*HH*TT, 256>>>(attnL);
        av_tc<<<gAV, thr>>>(attnL, v, o);

        gemm128<false,true,false,false><<<gC, thr, GSMEM>>>(o, CC, Wo + (size_t)l*CC*CC, CC,
                                                            bo + l*CC, h, CC, h, CC, CC, CC);

        ln_kernel<<<NTOK, 256>>>(h, ln3g + l*CC, ln3b + l*CC, hn);

        gemm128<true,false,true,false><<<gF1, thr, GSMEM>>>(hn, CC, W1 + (size_t)l*CC*FFD, FFD,
                                                            b1 + l*FFD, nullptr, 0, ff, FFP, FFD, CC);
        gemm128<false,true,false,true><<<gC, thr, GSMEM>>>(ff, FFP, W2 + (size_t)l*FFD*CC, CC,
                                                           b2 + l*CC, h, CC, h, CC, CC, FFD);
    }

    ln_kernel<<<NTOK, 256>>>(h, lnfg, lnfb, hn);
    gemm128<false,false,false,false><<<gL, thr, GSMEM>>>(hn, CC, Wout, VV,
                                                         bout, nullptr, 0, out_logits, VV, VV, CC);
}